// round 1
// baseline (speedup 1.0000x reference)
#include <cuda_runtime.h>
#include <math.h>

#define NNODES 50000
#define NEDGES 400000
#define FDIM   128
#define F3     384
#define NB     20

__device__ float g_h[(size_t)NNODES * FDIM];   // silu(ns@W1+b1)
__device__ float g_so[(size_t)NNODES * F3];    // scalar_out

// ---------------------------------------------------------------------------
// out = concat(node_scalar, node_vector)  (residuals accumulated by atomics)
// ---------------------------------------------------------------------------
__global__ void copy_init_kernel(const float4* __restrict__ ns,
                                 const float4* __restrict__ nv,
                                 float4* __restrict__ out) {
    const int NS4 = NNODES * FDIM / 4;          // 1.6M
    const int NT4 = NS4 + NNODES * F3 / 4;      // 6.4M
    int i = blockIdx.x * blockDim.x + threadIdx.x;
    if (i < NT4) out[i] = (i < NS4) ? ns[i] : nv[i - NS4];
}

// ---------------------------------------------------------------------------
// C[M,N] = act(A[M,K] @ W[K,N] + bias)   (register-tiled fp32 GEMM)
// BM=64, BN=64, BK=16, 256 threads, 4x4 per-thread tile
// ---------------------------------------------------------------------------
template<bool SILU>
__global__ __launch_bounds__(256)
void gemm_kernel(const float* __restrict__ A, const float* __restrict__ W,
                 const float* __restrict__ bias, float* __restrict__ C,
                 int M, int N, int K)
{
    const int BM = 64, BN = 64, BK = 16;
    __shared__ float As[BK][BM];
    __shared__ float Bs[BK][BN];

    int t  = threadIdx.x;
    int m0 = blockIdx.x * BM;
    int n0 = blockIdx.y * BN;
    int ty = t >> 4, tx = t & 15;

    // load indices
    int ar = t >> 2;            // 0..63 (A row within tile)
    int ak = (t & 3) << 2;      // 0,4,8,12 (A k-offset)
    int bk = t >> 4;            // 0..15
    int bn = (t & 15) << 2;     // 0..60

    float acc[4][4];
#pragma unroll
    for (int i = 0; i < 4; i++)
#pragma unroll
        for (int j = 0; j < 4; j++) acc[i][j] = 0.0f;

    for (int k0 = 0; k0 < K; k0 += BK) {
        float4 av = make_float4(0.f, 0.f, 0.f, 0.f);
        if (m0 + ar < M)
            av = *(const float4*)(A + (size_t)(m0 + ar) * K + k0 + ak);
        As[ak + 0][ar] = av.x;
        As[ak + 1][ar] = av.y;
        As[ak + 2][ar] = av.z;
        As[ak + 3][ar] = av.w;
        *(float4*)&Bs[bk][bn] = *(const float4*)(W + (size_t)(k0 + bk) * N + n0 + bn);
        __syncthreads();
#pragma unroll
        for (int k = 0; k < BK; k++) {
            float4 a4 = *(float4*)&As[k][ty << 2];
            float4 b4 = *(float4*)&Bs[k][tx << 2];
            float a[4] = {a4.x, a4.y, a4.z, a4.w};
            float b[4] = {b4.x, b4.y, b4.z, b4.w};
#pragma unroll
            for (int i = 0; i < 4; i++)
#pragma unroll
                for (int j = 0; j < 4; j++) acc[i][j] += a[i] * b[j];
        }
        __syncthreads();
    }

    float4 bb = *(const float4*)(bias + n0 + (tx << 2));
    float bv[4] = {bb.x, bb.y, bb.z, bb.w};
#pragma unroll
    for (int i = 0; i < 4; i++) {
        int m = m0 + (ty << 2) + i;
        if (m < M) {
            float v[4];
#pragma unroll
            for (int j = 0; j < 4; j++) {
                float x = acc[i][j] + bv[j];
                if (SILU) x = x / (1.0f + expf(-x));   // x * sigmoid(x)
                v[j] = x;
            }
            float4 o = make_float4(v[0], v[1], v[2], v[3]);
            *(float4*)(C + (size_t)m * N + n0 + (tx << 2)) = o;
        }
    }
}

// ---------------------------------------------------------------------------
// vector reduction (no return) : out[0..3] += v
// ---------------------------------------------------------------------------
__device__ __forceinline__ void red_add4(float* p, float4 v) {
    asm volatile("red.global.add.v4.f32 [%0], {%1, %2, %3, %4};"
                 :: "l"(p), "f"(v.x), "f"(v.y), "f"(v.z), "f"(v.w)
                 : "memory");
}

// ---------------------------------------------------------------------------
// Edge kernel: 32 edges / block of 256 threads.
//  Phase 1: load edge meta + W_filter (smem), compute sine basis.
//  Phase 2: mini-GEMM fw = basis @ W_filter (register tile 4 edges x 12 cols,
//           cols = c..c+3 in each of the 3 split groups), epilogue applies
//           cutoff * scalar_out[src] gather, then message math + red.v4
//           scatter — all without leaving registers.
// ---------------------------------------------------------------------------
__global__ __launch_bounds__(256)
void edge_kernel(const int2*  __restrict__ eidx,
                 const float* __restrict__ edist,
                 const float* __restrict__ ediff,
                 const float* __restrict__ Wf,      // [NB][384]
                 const float* __restrict__ bf,      // [384]
                 const float* __restrict__ nvec,    // [N,3,128]
                 const float* __restrict__ so,      // [N,384]
                 float* __restrict__ out_s,         // [N,128]
                 float* __restrict__ out_v)         // [N,3,128]
{
    __shared__ float s_Wf[NB * F3];        // 30720 B
    __shared__ float s_basis[32 * NB];     // 2560 B
    __shared__ float s_d[32], s_cut[32];
    __shared__ int   s_src[32], s_dst[32];
    __shared__ float s_unit[3][32];

    const float PI_C = 0.628318530717958648f;   // pi / 5

    int t  = threadIdx.x;
    int e0 = blockIdx.x << 5;

    // stage W_filter (L2-resident broadcast)
    for (int i = t; i < NB * F3 / 4; i += 256)
        ((float4*)s_Wf)[i] = ((const float4*)Wf)[i];

    if (t < 32) {
        int e = e0 + t;
        int2 ei = eidx[e];
        s_dst[t] = ei.x;               // dst = edge_idx[:,0]
        s_src[t] = ei.y;               // src = edge_idx[:,1]
        float d = edist[e];
        s_d[t] = d;
        s_cut[t] = (d < 5.0f) ? 0.5f * (cosf(d * PI_C) + 1.0f) : 0.0f;
        float inv = 1.0f / d;
        s_unit[0][t] = ediff[e * 3 + 0] * inv;
        s_unit[1][t] = ediff[e * 3 + 1] * inv;
        s_unit[2][t] = ediff[e * 3 + 2] * inv;
    }
    __syncthreads();

    // sine basis: sin(d * n * pi/5) / d, with explicit range reduction so
    // fast-math sin.approx stays accurate for large arguments
    for (int i = t; i < 32 * NB; i += 256) {
        int e = i / NB, n = i % NB;
        float d = s_d[e];
        float x = d * (float)(n + 1) * PI_C;
        x -= 6.2831853071795865f * rintf(x * 0.15915494309189534f);
        s_basis[i] = sinf(x) / d;
    }
    __syncthreads();

    int cg = t & 31;          // column group (lane)
    int eg = t >> 5;          // edge group (warp): edges eg*4 .. eg*4+3
    int cb = cg << 2;         // base channel 0..124

    float acc[4][12];
#pragma unroll
    for (int i = 0; i < 4; i++)
#pragma unroll
        for (int j = 0; j < 12; j++) acc[i][j] = 0.0f;

    const float* bas = &s_basis[(eg << 2) * NB];
#pragma unroll
    for (int k = 0; k < NB; k++) {
        float be[4];
#pragma unroll
        for (int i = 0; i < 4; i++) be[i] = bas[i * NB + k];
        float4 w0 = *(float4*)&s_Wf[k * F3 + cb];
        float4 w1 = *(float4*)&s_Wf[k * F3 + FDIM + cb];
        float4 w2 = *(float4*)&s_Wf[k * F3 + 2 * FDIM + cb];
#pragma unroll
        for (int i = 0; i < 4; i++) {
            acc[i][0] += be[i] * w0.x; acc[i][1] += be[i] * w0.y;
            acc[i][2] += be[i] * w0.z; acc[i][3] += be[i] * w0.w;
            acc[i][4] += be[i] * w1.x; acc[i][5] += be[i] * w1.y;
            acc[i][6] += be[i] * w1.z; acc[i][7] += be[i] * w1.w;
            acc[i][8] += be[i] * w2.x; acc[i][9] += be[i] * w2.y;
            acc[i][10]+= be[i] * w2.z; acc[i][11]+= be[i] * w2.w;
        }
    }

    float4 bf0 = *(const float4*)&bf[cb];
    float4 bf1 = *(const float4*)&bf[FDIM + cb];
    float4 bf2 = *(const float4*)&bf[2 * FDIM + cb];

#pragma unroll
    for (int i = 0; i < 4; i++) {
        int e   = (eg << 2) + i;
        int src = s_src[e];
        int dst = s_dst[e];
        float cw = s_cut[e];

        const float* sor = so + (size_t)src * F3;
        float4 s0 = *(const float4*)(sor + cb);
        float4 s1 = *(const float4*)(sor + FDIM + cb);
        float4 s2 = *(const float4*)(sor + 2 * FDIM + cb);

        float4 gs, ge, ms;
        gs.x = (acc[i][0] + bf0.x) * cw * s0.x;
        gs.y = (acc[i][1] + bf0.y) * cw * s0.y;
        gs.z = (acc[i][2] + bf0.z) * cw * s0.z;
        gs.w = (acc[i][3] + bf0.w) * cw * s0.w;
        ge.x = (acc[i][4] + bf1.x) * cw * s1.x;
        ge.y = (acc[i][5] + bf1.y) * cw * s1.y;
        ge.z = (acc[i][6] + bf1.z) * cw * s1.z;
        ge.w = (acc[i][7] + bf1.w) * cw * s1.w;
        ms.x = (acc[i][8] + bf2.x) * cw * s2.x;
        ms.y = (acc[i][9] + bf2.y) * cw * s2.y;
        ms.z = (acc[i][10]+ bf2.z) * cw * s2.z;
        ms.w = (acc[i][11]+ bf2.w) * cw * s2.w;

        // residual_scalar
        red_add4(out_s + (size_t)dst * FDIM + cb, ms);

        // residual_vector: nv[src][d][c]*gs[c] + ge[c]*unit[d]
        const float* nvp = nvec + (size_t)src * F3;
        float u0 = s_unit[0][e], u1 = s_unit[1][e], u2 = s_unit[2][e];

        float4 v, m;
        v = *(const float4*)(nvp + cb);
        m.x = v.x * gs.x + ge.x * u0;  m.y = v.y * gs.y + ge.y * u0;
        m.z = v.z * gs.z + ge.z * u0;  m.w = v.w * gs.w + ge.w * u0;
        red_add4(out_v + (size_t)dst * F3 + cb, m);

        v = *(const float4*)(nvp + FDIM + cb);
        m.x = v.x * gs.x + ge.x * u1;  m.y = v.y * gs.y + ge.y * u1;
        m.z = v.z * gs.z + ge.z * u1;  m.w = v.w * gs.w + ge.w * u1;
        red_add4(out_v + (size_t)dst * F3 + FDIM + cb, m);

        v = *(const float4*)(nvp + 2 * FDIM + cb);
        m.x = v.x * gs.x + ge.x * u2;  m.y = v.y * gs.y + ge.y * u2;
        m.z = v.z * gs.z + ge.z * u2;  m.w = v.w * gs.w + ge.w * u2;
        red_add4(out_v + (size_t)dst * F3 + 2 * FDIM + cb, m);
    }
}

// ---------------------------------------------------------------------------
extern "C" void kernel_launch(void* const* d_in, const int* in_sizes, int n_in,
                              void* d_out, int out_size) {
    const int2*  eidx  = (const int2*) d_in[0];
    const float* edist = (const float*)d_in[1];
    const float* ediff = (const float*)d_in[2];
    const float* ns    = (const float*)d_in[3];
    const float* nv    = (const float*)d_in[4];
    const float* Wf    = (const float*)d_in[5];
    const float* bf    = (const float*)d_in[6];
    const float* W1    = (const float*)d_in[7];
    const float* b1    = (const float*)d_in[8];
    const float* W2    = (const float*)d_in[9];
    const float* b2    = (const float*)d_in[10];
    float* out = (float*)d_out;

    float *h_ptr, *so_ptr;
    cudaGetSymbolAddress((void**)&h_ptr,  g_h);
    cudaGetSymbolAddress((void**)&so_ptr, g_so);

    // 1) out = concat(node_scalar, node_vector)
    int tot4 = (NNODES * FDIM + NNODES * F3) / 4;
    copy_init_kernel<<<(tot4 + 255) / 256, 256>>>(
        (const float4*)ns, (const float4*)nv, (float4*)out);

    // 2) h = silu(ns @ W1 + b1)
    gemm_kernel<true><<<dim3((NNODES + 63) / 64, FDIM / 64), 256>>>(
        ns, W1, b1, h_ptr, NNODES, FDIM, FDIM);

    // 3) scalar_out = h @ W2 + b2
    gemm_kernel<false><<<dim3((NNODES + 63) / 64, F3 / 64), 256>>>(
        h_ptr, W2, b2, so_ptr, NNODES, F3, FDIM);

    // 4) edge messages + scatter-add residuals
    edge_kernel<<<NEDGES / 32, 256>>>(
        eidx, edist, ediff, Wf, bf, nv, so_ptr,
        out, out + (size_t)NNODES * FDIM);
}